// round 1
// baseline (speedup 1.0000x reference)
#include <cuda_runtime.h>
#include <math.h>

#define BB    64
#define NN    2048
#define DIM   768
#define POOL  1024
#define LEN   16
#define ROW   2080          // 2*LEN + NN
#define NCHUNK 8
#define CH    256           // NN / NCHUNK
#define D4    192           // DIM / 4

// ---------------- scratch (device globals: no allocation allowed) ----------
__device__ __align__(16) float g_part[NCHUNK * BB * DIM];   // partial sums for mean
__device__ __align__(16) float g_xnorm[BB * DIM];           // l2norm(mean(x))
__device__ __align__(16) float g_pn[POOL * DIM];            // l2norm(prompt_key)
__device__ __align__(16) float g_rn[POOL * DIM];            // l2norm(residual_prompt_key)
__device__ int   g_idx[BB];
__device__ int   g_ridx[BB];
__device__ float g_maxsim[BB];
__device__ float g_rmaxsim[BB];

__device__ __forceinline__ float warp_sum(float v) {
    #pragma unroll
    for (int o = 16; o > 0; o >>= 1) v += __shfl_xor_sync(0xffffffffu, v, o);
    return v;
}

// ---------------------------------------------------------------------------
// K1: stream x_embed -> out[:, 32:, :] while accumulating partial sums
// grid (BB, NCHUNK), 192 threads (one float4 column each)
// ---------------------------------------------------------------------------
__global__ void k_mean_copy(const float* __restrict__ x, float* __restrict__ out) {
    const int t = threadIdx.x;            // 0..191
    const int b = blockIdx.x;             // 0..63
    const int z = blockIdx.y;             // 0..7

    const float4* src = reinterpret_cast<const float4*>(
        x + ((size_t)b * NN + (size_t)z * CH) * DIM) + t;
    float4* dst = reinterpret_cast<float4*>(
        out + ((size_t)b * ROW + 2 * LEN + (size_t)z * CH) * DIM) + t;

    float4 s = make_float4(0.f, 0.f, 0.f, 0.f);
    #pragma unroll 8
    for (int n = 0; n < CH; n++) {
        float4 v = src[(size_t)n * D4];
        s.x += v.x; s.y += v.y; s.z += v.z; s.w += v.w;
        dst[(size_t)n * D4] = v;
    }
    reinterpret_cast<float4*>(g_part)[((size_t)z * BB + b) * D4 + t] = s;
}

// ---------------------------------------------------------------------------
// K2: normalize rows. blocks: [0,POOL) prompt_key -> g_pn,
// [POOL,2*POOL) residual_prompt_key -> g_rn, [2*POOL,2*POOL+BB) x mean -> g_xnorm
// 192 threads / block (6 warps)
// ---------------------------------------------------------------------------
__global__ void k_normalize(const float* __restrict__ pk,
                            const float* __restrict__ rpk) {
    const int r = blockIdx.x;
    const int t = threadIdx.x;            // 0..191
    const int w = t >> 5, lane = t & 31;

    float4 v;
    float* dst;
    if (r < POOL) {
        v = reinterpret_cast<const float4*>(pk + (size_t)r * DIM)[t];
        dst = g_pn + (size_t)r * DIM;
    } else if (r < 2 * POOL) {
        v = reinterpret_cast<const float4*>(rpk + (size_t)(r - POOL) * DIM)[t];
        dst = g_rn + (size_t)(r - POOL) * DIM;
    } else {
        const int b = r - 2 * POOL;
        float4 acc = make_float4(0.f, 0.f, 0.f, 0.f);
        #pragma unroll
        for (int z = 0; z < NCHUNK; z++) {
            float4 p = reinterpret_cast<const float4*>(g_part)[((size_t)z * BB + b) * D4 + t];
            acc.x += p.x; acc.y += p.y; acc.z += p.z; acc.w += p.w;
        }
        const float inv = 1.0f / (float)NN;
        v = make_float4(acc.x * inv, acc.y * inv, acc.z * inv, acc.w * inv);
        dst = g_xnorm + (size_t)b * DIM;
    }

    float ss = v.x * v.x + v.y * v.y + v.z * v.z + v.w * v.w;
    ss = warp_sum(ss);
    __shared__ float sm[6];
    __shared__ float s_rinv;
    if (lane == 0) sm[w] = ss;
    __syncthreads();
    if (t == 0) {
        float tot = 0.f;
        #pragma unroll
        for (int i = 0; i < 6; i++) tot += sm[i];
        s_rinv = 1.0f / sqrtf(fmaxf(tot, 1e-12f));
    }
    __syncthreads();
    const float rinv = s_rinv;
    reinterpret_cast<float4*>(dst)[t] = make_float4(v.x * rinv, v.y * rinv, v.z * rinv, v.w * rinv);
}

// ---------------------------------------------------------------------------
// argmax over POOL keys for a query row held in smem (tie -> lowest index,
// matching jax.lax.top_k). 256 threads, warp-per-prompt stride 8.
// ---------------------------------------------------------------------------
__device__ __forceinline__ void argmax_keys(const float* __restrict__ keys,
                                            const float4* __restrict__ qs,  // smem, D4 float4
                                            int b, int* out_idx, float* out_val) {
    const int t = threadIdx.x;
    const int w = t >> 5, lane = t & 31;

    float best = -3.4e38f;
    int bestp = 0;
    for (int p = w; p < POOL; p += 8) {
        const float4* row = reinterpret_cast<const float4*>(keys + (size_t)p * DIM);
        float acc = 0.f;
        #pragma unroll
        for (int j = 0; j < 6; j++) {
            float4 a = row[lane + 32 * j];
            float4 q = qs[lane + 32 * j];
            acc += a.x * q.x + a.y * q.y + a.z * q.z + a.w * q.w;
        }
        acc = warp_sum(acc);                    // all lanes hold full dot
        if (acc > best) { best = acc; bestp = p; }   // p ascending -> earliest on tie
    }

    __shared__ float bsm[8];
    __shared__ int   psm[8];
    if (lane == 0) { bsm[w] = best; psm[w] = bestp; }
    __syncthreads();
    if (t == 0) {
        float bv = bsm[0]; int bp = psm[0];
        #pragma unroll
        for (int i = 1; i < 8; i++) {
            if (bsm[i] > bv || (bsm[i] == bv && psm[i] < bp)) { bv = bsm[i]; bp = psm[i]; }
        }
        out_idx[b] = bp;
        out_val[b] = bv;
    }
}

// K3: sim = x_norm @ pn^T, top-1 per b
__global__ void k_sim() {
    const int b = blockIdx.x;
    const int t = threadIdx.x;
    __shared__ float4 qs[D4];
    if (t < D4) qs[t] = reinterpret_cast<const float4*>(g_xnorm + (size_t)b * DIM)[t];
    __syncthreads();
    argmax_keys(g_pn, qs, b, g_idx, g_maxsim);
}

// K4: residual = prompt_key[idx[b]] - x_norm[b]; top-1 over rn
__global__ void k_res_sim(const float* __restrict__ pk) {
    const int b = blockIdx.x;
    const int t = threadIdx.x;
    __shared__ float4 qs[D4];
    __shared__ int s_idx;
    if (t == 0) s_idx = g_idx[b];
    __syncthreads();
    const int idx = s_idx;
    if (t < D4) {
        float4 a = reinterpret_cast<const float4*>(pk + (size_t)idx * DIM)[t];
        float4 xn = reinterpret_cast<const float4*>(g_xnorm + (size_t)b * DIM)[t];
        qs[t] = make_float4(a.x - xn.x, a.y - xn.y, a.z - xn.z, a.w - xn.w);
    }
    __syncthreads();
    argmax_keys(g_rn, qs, b, g_ridx, g_rmaxsim);
}

// ---------------------------------------------------------------------------
// K5: gather winning prompts into out[:, 0:32, :] + write scalar loss
// ---------------------------------------------------------------------------
__global__ void k_gather(const float* __restrict__ prompt,
                         const float* __restrict__ rprompt,
                         float* __restrict__ out,
                         long long out_size) {
    const int b = blockIdx.x;
    const int t = threadIdx.x;            // 256 threads
    const int idx  = g_idx[b];
    const int ridx = g_ridx[b];

    const float4* s1 = reinterpret_cast<const float4*>(rprompt + (size_t)ridx * LEN * DIM);
    const float4* s2 = reinterpret_cast<const float4*>(prompt  + (size_t)idx  * LEN * DIM);
    float4* dst = reinterpret_cast<float4*>(out + (size_t)b * ROW * DIM);

    const int SEG = LEN * DIM / 4;        // 3072
    #pragma unroll 4
    for (int i = t; i < SEG; i += 256) dst[i] = s1[i];
    #pragma unroll 4
    for (int i = t; i < SEG; i += 256) dst[SEG + i] = s2[i];

    if (b == 0 && t == 0) {
        float s = 0.f;
        for (int i = 0; i < BB; i++) s += g_maxsim[i] + g_rmaxsim[i];
        s *= (1.0f / (float)BB);
        const size_t np = (size_t)BB * ROW * DIM;
        if ((size_t)out_size > np) out[(size_t)out_size - 1] = s;
    }
}

// ---------------------------------------------------------------------------
extern "C" void kernel_launch(void* const* d_in, const int* in_sizes, int n_in,
                              void* d_out, int out_size) {
    const float* x       = (const float*)d_in[0];   // [64,2048,768]
    const float* prompt  = (const float*)d_in[1];   // [1024,16,768]
    const float* pk      = (const float*)d_in[2];   // [1024,768]
    const float* rprompt = (const float*)d_in[3];   // [1024,16,768]
    const float* rpk     = (const float*)d_in[4];   // [1024,768]
    float* out = (float*)d_out;

    k_mean_copy<<<dim3(BB, NCHUNK), D4>>>(x, out);
    k_normalize<<<2 * POOL + BB, D4>>>(pk, rpk);
    k_sim<<<BB, 256>>>();
    k_res_sim<<<BB, 256>>>(pk);
    k_gather<<<BB, 256>>>(prompt, rprompt, out, (long long)out_size);
}

// round 3
// speedup vs baseline: 1.1461x; 1.1461x over previous
#include <cuda_runtime.h>
#include <math.h>

#define BB    64
#define NN    2048
#define DIM   768
#define POOL  1024
#define LEN   16
#define ROW   2080          // 2*LEN + NN
#define NCHUNK 8
#define CH    256           // NN / NCHUNK
#define D4    192           // DIM / 4
#define PCH   4             // prompt chunks (POOL / 256)

// ---------------- scratch (device globals; only referenced in device code) --
__device__ __align__(16) float g_part[NCHUNK * BB * DIM];
__device__ __align__(16) float g_xnorm[BB * DIM];
__device__ __align__(16) float g_resq[BB * DIM];
__device__ __align__(16) float g_pn[POOL * DIM];
__device__ __align__(16) float g_rn[POOL * DIM];
__device__ float g_cval[BB * PCH];
__device__ int   g_cidx[BB * PCH];
__device__ float g_rcval[BB * PCH];
__device__ int   g_rcidx[BB * PCH];
__device__ int   g_idx[BB];
__device__ float g_maxsim[BB];

__device__ __forceinline__ float warp_sum(float v) {
    #pragma unroll
    for (int o = 16; o > 0; o >>= 1) v += __shfl_xor_sync(0xffffffffu, v, o);
    return v;
}

// ---------------------------------------------------------------------------
// K1: stream x_embed -> out[:, 32:, :] while accumulating partial sums
// ---------------------------------------------------------------------------
__global__ void k_mean_copy(const float* __restrict__ x, float* __restrict__ out) {
    const int t = threadIdx.x;            // 0..191
    const int b = blockIdx.x;
    const int z = blockIdx.y;

    const float4* src = reinterpret_cast<const float4*>(
        x + ((size_t)b * NN + (size_t)z * CH) * DIM) + t;
    float4* dst = reinterpret_cast<float4*>(
        out + ((size_t)b * ROW + 2 * LEN + (size_t)z * CH) * DIM) + t;

    float4 s = make_float4(0.f, 0.f, 0.f, 0.f);
    #pragma unroll 8
    for (int n = 0; n < CH; n++) {
        float4 v = src[(size_t)n * D4];
        s.x += v.x; s.y += v.y; s.z += v.z; s.w += v.w;
        dst[(size_t)n * D4] = v;
    }
    reinterpret_cast<float4*>(g_part)[((size_t)z * BB + b) * D4 + t] = s;
}

// ---------------------------------------------------------------------------
// K2: normalize rows (prompt_key -> g_pn, residual_key -> g_rn, mean -> g_xnorm)
// ---------------------------------------------------------------------------
__global__ void k_normalize(const float* __restrict__ pk,
                            const float* __restrict__ rpk) {
    const int r = blockIdx.x;
    const int t = threadIdx.x;            // 0..191
    const int w = t >> 5, lane = t & 31;

    float4 v;
    float* dst;
    if (r < POOL) {
        v = reinterpret_cast<const float4*>(pk + (size_t)r * DIM)[t];
        dst = g_pn + (size_t)r * DIM;
    } else if (r < 2 * POOL) {
        v = reinterpret_cast<const float4*>(rpk + (size_t)(r - POOL) * DIM)[t];
        dst = g_rn + (size_t)(r - POOL) * DIM;
    } else {
        const int b = r - 2 * POOL;
        float4 acc = make_float4(0.f, 0.f, 0.f, 0.f);
        #pragma unroll
        for (int z = 0; z < NCHUNK; z++) {
            float4 p = reinterpret_cast<const float4*>(g_part)[((size_t)z * BB + b) * D4 + t];
            acc.x += p.x; acc.y += p.y; acc.z += p.z; acc.w += p.w;
        }
        const float inv = 1.0f / (float)NN;
        v = make_float4(acc.x * inv, acc.y * inv, acc.z * inv, acc.w * inv);
        dst = g_xnorm + (size_t)b * DIM;
    }

    float ss = v.x * v.x + v.y * v.y + v.z * v.z + v.w * v.w;
    ss = warp_sum(ss);
    __shared__ float sm[6];
    __shared__ float s_rinv;
    if (lane == 0) sm[w] = ss;
    __syncthreads();
    if (t == 0) {
        float tot = 0.f;
        #pragma unroll
        for (int i = 0; i < 6; i++) tot += sm[i];
        s_rinv = 1.0f / sqrtf(fmaxf(tot, 1e-12f));
    }
    __syncthreads();
    const float rinv = s_rinv;
    reinterpret_cast<float4*>(dst)[t] = make_float4(v.x * rinv, v.y * rinv, v.z * rinv, v.w * rinv);
}

// ---------------------------------------------------------------------------
// K3/K5: partial argmax, one prompt per thread. grid (BB, PCH), 256 threads.
// which=0: keys=g_pn, q=g_xnorm -> g_cval/g_cidx
// which=1: keys=g_rn, q=g_resq  -> g_rcval/g_rcidx
// Tie rule: equal value -> lower prompt index (jax top_k).
// ---------------------------------------------------------------------------
__global__ void k_argmax_part(int which) {
    const int b = blockIdx.x;
    const int pc = blockIdx.y;
    const int t = threadIdx.x;            // 0..255

    const float* keys  = which ? g_rn   : g_pn;
    const float* qbase = which ? g_resq : g_xnorm;
    float* cval = which ? g_rcval : g_cval;
    int*   cidx = which ? g_rcidx : g_cidx;

    __shared__ float4 qs[D4];
    if (t < D4) qs[t] = reinterpret_cast<const float4*>(qbase + (size_t)b * DIM)[t];
    __syncthreads();

    const int p = pc * 256 + t;
    const float4* row = reinterpret_cast<const float4*>(keys + (size_t)p * DIM);

    float a0 = 0.f, a1 = 0.f, a2 = 0.f, a3 = 0.f;
    #pragma unroll 4
    for (int j = 0; j < D4; j += 4) {
        float4 r0 = row[j + 0], q0 = qs[j + 0];
        float4 r1 = row[j + 1], q1 = qs[j + 1];
        float4 r2 = row[j + 2], q2 = qs[j + 2];
        float4 r3 = row[j + 3], q3 = qs[j + 3];
        a0 += r0.x * q0.x + r0.y * q0.y + r0.z * q0.z + r0.w * q0.w;
        a1 += r1.x * q1.x + r1.y * q1.y + r1.z * q1.z + r1.w * q1.w;
        a2 += r2.x * q2.x + r2.y * q2.y + r2.z * q2.z + r2.w * q2.w;
        a3 += r3.x * q3.x + r3.y * q3.y + r3.z * q3.z + r3.w * q3.w;
    }
    float v = (a0 + a1) + (a2 + a3);

    __shared__ float sv[256];
    __shared__ int   si[256];
    sv[t] = v; si[t] = p;
    __syncthreads();
    #pragma unroll
    for (int s = 128; s > 0; s >>= 1) {
        if (t < s) {
            float ov = sv[t + s]; int oi = si[t + s];
            if (ov > sv[t] || (ov == sv[t] && oi < si[t])) { sv[t] = ov; si[t] = oi; }
        }
        __syncthreads();
    }
    if (t == 0) { cval[b * PCH + pc] = sv[0]; cidx[b * PCH + pc] = si[0]; }
}

// ---------------------------------------------------------------------------
// K4: reduce first-level candidates, build residual query. grid BB, 192 thr.
// ---------------------------------------------------------------------------
__global__ void k_reduce_res(const float* __restrict__ pk) {
    const int b = blockIdx.x;
    const int t = threadIdx.x;            // 0..191
    __shared__ int s_idx;
    if (t == 0) {
        float bv = g_cval[b * PCH]; int bi = g_cidx[b * PCH];
        #pragma unroll
        for (int c = 1; c < PCH; c++) {
            float ov = g_cval[b * PCH + c]; int oi = g_cidx[b * PCH + c];
            if (ov > bv || (ov == bv && oi < bi)) { bv = ov; bi = oi; }
        }
        g_idx[b] = bi;
        g_maxsim[b] = bv;
        s_idx = bi;
    }
    __syncthreads();
    const int idx = s_idx;
    float4 a  = reinterpret_cast<const float4*>(pk + (size_t)idx * DIM)[t];
    float4 xn = reinterpret_cast<const float4*>(g_xnorm + (size_t)b * DIM)[t];
    reinterpret_cast<float4*>(g_resq + (size_t)b * DIM)[t] =
        make_float4(a.x - xn.x, a.y - xn.y, a.z - xn.z, a.w - xn.w);
}

// ---------------------------------------------------------------------------
// K6: gather winning prompts + scalar loss. grid BB, 256 threads.
// ---------------------------------------------------------------------------
__device__ __forceinline__ void reduce_rcand(int b, float* bv, int* bi) {
    float v = g_rcval[b * PCH]; int i = g_rcidx[b * PCH];
    #pragma unroll
    for (int c = 1; c < PCH; c++) {
        float ov = g_rcval[b * PCH + c]; int oi = g_rcidx[b * PCH + c];
        if (ov > v || (ov == v && oi < i)) { v = ov; i = oi; }
    }
    *bv = v; *bi = i;
}

__global__ void k_gather(const float* __restrict__ prompt,
                         const float* __restrict__ rprompt,
                         float* __restrict__ out,
                         long long out_size) {
    const int b = blockIdx.x;
    const int t = threadIdx.x;            // 256 threads
    __shared__ int s_ridx;
    if (t == 0) {
        float rv; int ri;
        reduce_rcand(b, &rv, &ri);
        s_ridx = ri;
    }
    __syncthreads();
    const int idx  = g_idx[b];
    const int ridx = s_ridx;

    const float4* s1 = reinterpret_cast<const float4*>(rprompt + (size_t)ridx * LEN * DIM);
    const float4* s2 = reinterpret_cast<const float4*>(prompt  + (size_t)idx  * LEN * DIM);
    float4* dst = reinterpret_cast<float4*>(out + (size_t)b * ROW * DIM);

    const int SEG = LEN * DIM / 4;        // 3072
    #pragma unroll 4
    for (int i = t; i < SEG; i += 256) dst[i] = s1[i];
    #pragma unroll 4
    for (int i = t; i < SEG; i += 256) dst[SEG + i] = s2[i];

    if (b == 0 && t == 0) {
        float s = 0.f;
        for (int i = 0; i < BB; i++) {
            float rv; int ri;
            reduce_rcand(i, &rv, &ri);
            s += g_maxsim[i] + rv;
        }
        s *= (1.0f / (float)BB);
        const size_t np = (size_t)BB * ROW * DIM;
        if ((size_t)out_size > np) out[(size_t)out_size - 1] = s;
    }
}

// ---------------------------------------------------------------------------
extern "C" void kernel_launch(void* const* d_in, const int* in_sizes, int n_in,
                              void* d_out, int out_size) {
    const float* x       = (const float*)d_in[0];
    const float* prompt  = (const float*)d_in[1];
    const float* pk      = (const float*)d_in[2];
    const float* rprompt = (const float*)d_in[3];
    const float* rpk     = (const float*)d_in[4];
    float* out = (float*)d_out;

    k_mean_copy<<<dim3(BB, NCHUNK), D4>>>(x, out);
    k_normalize<<<2 * POOL + BB, D4>>>(pk, rpk);
    k_argmax_part<<<dim3(BB, PCH), 256>>>(0);
    k_reduce_res<<<BB, D4>>>(pk);
    k_argmax_part<<<dim3(BB, PCH), 256>>>(1);
    k_gather<<<BB, 256>>>(prompt, rprompt, out, (long long)out_size);
}